// round 15
// baseline (speedup 1.0000x reference)
#include <cuda_runtime.h>
#include <math.h>

#define NN    2048
#define EE    65536
#define SEQL  5
#define IND   32
#define HD    64
#define OUTD  16
#define EPSV  1e-5f
#define FULLM 0xffffffffu
#define AGGB  256          // agg blocks in fused kernel (8 nodes each); MUST be < min-residency (296)

// ---------------- scratch (device globals) ----------------
__device__ unsigned long long g_pk[NN];   // packed: cnt<<44 | fixed20(sum w); zeroed by k_scan each run
__device__ int      g_rank[EE];
__device__ int      g_rowptr[NN + 1];
__device__ float    g_dinv[NN];
__device__ float    g_dself[NN];
__device__ float2   g_csr[EE];            // (src as int bits, norm)
__device__ unsigned g_barc;               // fused-kernel agg barrier; zeroed by k_scan

__device__ float  g_Wzl[IND * HD];        // Wcz @ Wlz[:HD]
__device__ float  g_Whl[IND * HD];        // Wch @ Wlh[:HD]
__device__ float  g_biasz[HD];
__device__ float  g_biash[HD];

__device__ float  g_y  [SEQL * NN * IND]; // aggregated x: [t][n][32]
__device__ float  g_hw1[NN * HD];
__device__ float  g_hw2[NN * HD];
__device__ float  g_A  [NN * HD];
__device__ float  g_B  [NN * HD];
__device__ float  g_alpha[NN];
__device__ float  g_beta [NN];

// ---------------- K1: combined gate weights (blocks 0-1, smem-staged) + degree atomics ----------------
__global__ __launch_bounds__(256) void k_pre_deg(
    const float* __restrict__ Wcz, const float* __restrict__ bcz,
    const float* __restrict__ Wlz, const float* __restrict__ blz,
    const float* __restrict__ Wch, const float* __restrict__ bch,
    const float* __restrict__ Wlh, const float* __restrict__ blh,
    const int* __restrict__ ei,    const float* __restrict__ ew) {
    int b = blockIdx.x;
    int tid = threadIdx.x;
    if (b >= 2) {                     // degree + per-edge rank via one packed atomic
        int e = (b - 2) * 256 + tid;
        int dst = ei[EE + e];
        unsigned fixw = __float2uint_rn(ew[e] * 1048576.0f);   // w in [0,1)
        unsigned long long pk = (1ull << 44) | (unsigned long long)fixw;
        unsigned long long old = atomicAdd(&g_pk[dst], pk);
        g_rank[e] = (int)(old >> 44);
        return;
    }
    __shared__ __align__(16) float sWl[HD * HD];
    __shared__ __align__(16) float sWc[IND * HD];
    bool z = (b == 0);
    const float* Wc = z ? Wcz : Wch;
    const float* Wl = z ? Wlz : Wlh;
    const float* bc = z ? bcz : bch;
    const float* bl = z ? blz : blh;
    float* Wo = z ? g_Wzl : g_Whl;
    float* bo = z ? g_biasz : g_biash;
#pragma unroll
    for (int q = 0; q < 4; q++)
        ((float4*)sWl)[tid + 256 * q] = ((const float4*)Wl)[tid + 256 * q];
#pragma unroll
    for (int q = 0; q < 2; q++)
        ((float4*)sWc)[tid + 256 * q] = ((const float4*)Wc)[tid + 256 * q];
    __syncthreads();
#pragma unroll
    for (int q = 0; q < 8; q++) {
        int o = tid + 256 * q;        // o < 2048
        int i = o >> 6, k = o & 63;
        float acc = 0.f;
#pragma unroll 8
        for (int m = 0; m < HD; m++)
            acc = fmaf(sWc[i * HD + m], sWl[m * HD + k], acc);
        Wo[o] = acc;
    }
    if (tid < HD) {
        float acc = bl[tid];
#pragma unroll 8
        for (int m = 0; m < HD; m++)
            acc = fmaf(bc[m], sWl[m * HD + tid], acc);
        bo[tid] = acc;
    }
}

// ---------------- K2: scan counts -> rowptr; deg -> dinv/dself; re-zero g_pk + barrier ----------------
__global__ void k_scan() {
    __shared__ int s[1024];
    int t = threadIdx.x;
    if (t == 0) g_barc = 0u;          // reset fused-kernel barrier for this replay
    unsigned long long p0 = g_pk[2 * t];
    unsigned long long p1 = g_pk[2 * t + 1];
    g_pk[2 * t] = 0ull;               // reset for the next run (graph replay)
    g_pk[2 * t + 1] = 0ull;
    int a = (int)(p0 >> 44);
    int b = (int)(p1 >> 44);
    int pairsum = a + b;
    s[t] = pairsum;
    for (int off = 1; off < 1024; off <<= 1) {
        __syncthreads();
        int v = (t >= off) ? s[t - off] : 0;
        __syncthreads();
        s[t] += v;
    }
    __syncthreads();
    int incl = s[t];
    int excl = incl - pairsum;
    g_rowptr[2 * t]     = excl;
    g_rowptr[2 * t + 1] = excl + a;
    if (t == 1023) g_rowptr[NN] = incl;

    const float inv20 = 1.0f / 1048576.0f;
    const unsigned long long mask = (1ull << 44) - 1;
    float d0 = (float)(double)(p0 & mask) * inv20 + 1.0f;
    float d1 = (float)(double)(p1 & mask) * inv20 + 1.0f;
    float i0 = rsqrtf(d0), i1 = rsqrtf(d1);
    g_dinv[2 * t] = i0;      g_dself[2 * t] = i0 * i0;
    g_dinv[2 * t + 1] = i1;  g_dself[2 * t + 1] = i1 * i1;
}

// ---------------- K3: scatter (atomic-free; position known) ----------------
__global__ __launch_bounds__(256) void k_scatter(const int* __restrict__ ei,
                                                 const float* __restrict__ ew) {
    int e = blockIdx.x * 256 + threadIdx.x;
    int src = ei[e];
    int dst = ei[EE + e];
    int pos = g_rowptr[dst] + g_rank[e];
    g_csr[pos] = make_float2(__int_as_float(src),
                             g_dinv[src] * ew[e] * g_dinv[dst]);
}

// ---------------- K4: aggregate RAW x; warp = (node, edge-quarter), all 5 t ----------------
__global__ __launch_bounds__(256) void k_aggX(const float* __restrict__ x) {
    __shared__ float part[8][SEQL][32];      // 5KB
    int tid = threadIdx.x;
    int wid = tid >> 5;
    int l = tid & 31;                        // feature index
    int node = wid >> 2;                     // 0..1
    int q = wid & 3;
    int n = blockIdx.x * 2 + node;
    int beg = g_rowptr[n], end = g_rowptr[n + 1];
    int len = end - beg;
    int qbeg = beg + ((len * q) >> 2);
    int qend = beg + ((len * (q + 1)) >> 2);

    float a0 = 0.f, a1 = 0.f, a2 = 0.f, a3 = 0.f, a4 = 0.f;
    for (int base = qbeg; base < qend; base += 32) {
        int m = qend - base; if (m > 32) m = 32;
        float2 ce = (base + l < qend) ? g_csr[base + l] : make_float2(0.f, 0.f);
        int cs = __float_as_int(ce.x);
#pragma unroll 8
        for (int i = 0; i < m; i++) {
            int   s  = __shfl_sync(FULLM, cs, i);
            float wt = __shfl_sync(FULLM, ce.y, i);
            const float* xs = x + s * IND + l;
            a0 = fmaf(wt, xs[0 * NN * IND], a0);
            a1 = fmaf(wt, xs[1 * NN * IND], a1);
            a2 = fmaf(wt, xs[2 * NN * IND], a2);
            a3 = fmaf(wt, xs[3 * NN * IND], a3);
            a4 = fmaf(wt, xs[4 * NN * IND], a4);
        }
    }
    part[wid][0][l] = a0;
    part[wid][1][l] = a1;
    part[wid][2][l] = a2;
    part[wid][3][l] = a3;
    part[wid][4][l] = a4;
    __syncthreads();

    if (tid < 160) {
        int nd = tid >= 80 ? 1 : 0;
        int rem = tid - nd * 80;         // (t, l-pair): t = rem/16, l = (rem%16)*2
        int t  = rem / 16;
        int l2 = (rem % 16) * 2;
        int w0 = nd * 4;
        int n2 = blockIdx.x * 2 + nd;
        float ds = g_dself[n2];
#pragma unroll
        for (int u = 0; u < 2; u++) {
            int ll = l2 + u;
            float sv = part[w0][t][ll] + part[w0 + 1][t][ll]
                     + part[w0 + 2][t][ll] + part[w0 + 3][t][ll];
            sv = fmaf(ds, x[(t * NN + n2) * IND + ll], sv);
            g_y[(t * NN + n2) * IND + ll] = sv;
        }
    }
}

// ---------------- K5: gates + emb=H@Wred+bred; hw1/A/B; alpha/beta (16 nodes/block) ----------------
__global__ __launch_bounds__(256) void k_red_plus(
    const float* __restrict__ Wred, const float* __restrict__ bred,
    const float* __restrict__ Wc1,
    const float* __restrict__ Wi1,  const float* __restrict__ bi1,
    const float* __restrict__ Wi2) {
    __shared__ __align__(16) float sH[16 * SEQL * HD];  // 20KB
    __shared__ __align__(16) float wt[HD * HD];         // 16KB
    __shared__ __align__(16) union {
        float sy[16 * SEQL * IND];
        float sE[16 * HD];
    } u;
    __shared__ float sWi2[HD];
    __shared__ float red[8][4];
    int tid = threadIdx.x;
    int k = tid & 63;
    int rgrp = tid >> 6;
    int warpid = tid >> 5;
    int rowbase = blockIdx.x * 16;

#pragma unroll
    for (int t = 0; t < SEQL; t++) {
        if (tid < 128)
            ((float4*)(u.sy + t * 512))[tid] =
                ((const float4*)(g_y + (t * NN + rowbase) * IND))[tid];
    }
#pragma unroll
    for (int q = 0; q < 8; q++) {
        int idx = tid + 256 * q;
        ((float2*)wt)[idx] = make_float2(g_Wzl[idx], g_Whl[idx]);
    }
    if (tid < HD) sWi2[tid] = Wi2[tid];
    __syncthreads();

    {
        float bz = g_biasz[k], bh = g_biash[k];
#pragma unroll 4
        for (int rr = 0; rr < 20; rr++) {
            int rid = rgrp * 20 + rr;
            int t = rid >> 4, node = rid & 15;
            const float* yr = u.sy + (t * 16 + node) * IND;
            float az = bz, ah = bh;
#pragma unroll
            for (int i = 0; i < IND; i++) {
                float2 w2 = ((const float2*)wt)[i * HD + k];
                float yv = yr[i];
                az = fmaf(yv, w2.x, az);
                ah = fmaf(yv, w2.y, ah);
            }
            float Z  = 1.0f / (1.0f + expf(-az));
            float Ht = tanhf(ah);
            sH[node * (SEQL * HD) + t * HD + k] = (1.0f - Z) * Ht;
        }
    }
    __syncthreads();

    float acc[4];
    float br = bred[k];
#pragma unroll
    for (int rr = 0; rr < 4; rr++) acc[rr] = br;
    for (int c = 0; c < SEQL; c++) {
#pragma unroll
        for (int q = 0; q < 4; q++)
            ((float4*)wt)[tid + 256 * q] = ((const float4*)(Wred + c * HD * HD))[tid + 256 * q];
        __syncthreads();
#pragma unroll 8
        for (int i = 0; i < HD; i++) {
            float w = wt[i * HD + k];
#pragma unroll
            for (int rr = 0; rr < 4; rr++)
                acc[rr] = fmaf(sH[(rgrp * 4 + rr) * (SEQL * HD) + c * HD + i], w, acc[rr]);
        }
        __syncthreads();
    }
#pragma unroll
    for (int rr = 0; rr < 4; rr++)
        u.sE[(rgrp * 4 + rr) * HD + k] = acc[rr];

#pragma unroll
    for (int q = 0; q < 4; q++)
        ((float4*)wt)[tid + 256 * q] = ((const float4*)Wc1)[tid + 256 * q];
    __syncthreads();
#pragma unroll
    for (int rr = 0; rr < 4; rr++) acc[rr] = 0.f;
#pragma unroll 8
    for (int i = 0; i < HD; i++) {
        float w = wt[i * HD + k];
#pragma unroll
        for (int rr = 0; rr < 4; rr++)
            acc[rr] = fmaf(u.sE[(rgrp * 4 + rr) * HD + i], w, acc[rr]);
    }
#pragma unroll
    for (int rr = 0; rr < 4; rr++)
        g_hw1[(rowbase + rgrp * 4 + rr) * HD + k] = acc[rr];

    __syncthreads();
#pragma unroll
    for (int q = 0; q < 4; q++)
        ((float4*)wt)[tid + 256 * q] = ((const float4*)Wi1)[tid + 256 * q];
    __syncthreads();
    float b1 = bi1[k];
#pragma unroll
    for (int rr = 0; rr < 4; rr++) acc[rr] = b1;
#pragma unroll 8
    for (int i = 0; i < HD; i++) {
        float w = wt[i * HD + k];
#pragma unroll
        for (int rr = 0; rr < 4; rr++)
            acc[rr] = fmaf(u.sE[(rgrp * 4 + rr) * HD + i], w, acc[rr]);
    }
    {
        float w2 = sWi2[k];
        float pa[4];
#pragma unroll
        for (int rr = 0; rr < 4; rr++) {
            g_A[(rowbase + rgrp * 4 + rr) * HD + k] = acc[rr];
            pa[rr] = acc[rr] * w2;
#pragma unroll
            for (int off = 16; off > 0; off >>= 1)
                pa[rr] += __shfl_xor_sync(FULLM, pa[rr], off);
        }
        if ((tid & 31) == 0)
#pragma unroll
            for (int rr = 0; rr < 4; rr++) red[warpid][rr] = pa[rr];
        __syncthreads();
        if (k < 4)
            g_alpha[rowbase + rgrp * 4 + k] = red[rgrp * 2][k] + red[rgrp * 2 + 1][k];
    }

    __syncthreads();
#pragma unroll
    for (int q = 0; q < 4; q++)
        ((float4*)wt)[tid + 256 * q] = ((const float4*)(Wi1 + HD * HD))[tid + 256 * q];
    __syncthreads();
#pragma unroll
    for (int rr = 0; rr < 4; rr++) acc[rr] = 0.f;
#pragma unroll 8
    for (int i = 0; i < HD; i++) {
        float w = wt[i * HD + k];
#pragma unroll
        for (int rr = 0; rr < 4; rr++)
            acc[rr] = fmaf(u.sE[(rgrp * 4 + rr) * HD + i], w, acc[rr]);
    }
    {
        float w2 = sWi2[k];
        float pb[4];
#pragma unroll
        for (int rr = 0; rr < 4; rr++) {
            g_B[(rowbase + rgrp * 4 + rr) * HD + k] = acc[rr];
            pb[rr] = acc[rr] * w2;
#pragma unroll
            for (int off = 16; off > 0; off >>= 1)
                pb[rr] += __shfl_xor_sync(FULLM, pb[rr], off);
        }
        __syncthreads();
        if ((tid & 31) == 0)
#pragma unroll
            for (int rr = 0; rr < 4; rr++) red[warpid][rr] = pb[rr];
        __syncthreads();
        if (k < 4)
            g_beta[rowbase + rgrp * 4 + k] = red[rgrp * 2][k] + red[rgrp * 2 + 1][k];
    }
}

// ---------------- helpers ----------------
__device__ __forceinline__ float agg_edge64(const float* __restrict__ feat,
                                            int n, int k, int l) {
    int beg = g_rowptr[n], end = g_rowptr[n + 1];
    float sum = 0.f;
    for (int base = beg; base < end; base += 32) {
        int m = end - base; if (m > 32) m = 32;
        float2 ce = (base + l < end) ? g_csr[base + l] : make_float2(0.f, 0.f);
        int   cs = __float_as_int(ce.x);
        for (int i = 0; i < m; i++) {
            int   s  = __shfl_sync(FULLM, cs, i);
            float wt = __shfl_sync(FULLM, ce.y, i);
            sum = fmaf(wt, feat[s * HD + k], sum);
        }
    }
    return sum;
}

__device__ __forceinline__ float gsum64(float v, float* slots, int g, int tid) {
#pragma unroll
    for (int off = 16; off > 0; off >>= 1)
        v += __shfl_xor_sync(FULLM, v, off);
    if ((tid & 31) == 0) slots[tid >> 5] = v;
    __syncthreads();
    return slots[g * 2] + slots[g * 2 + 1];
}

__device__ __forceinline__ void lds2(unsigned long long& x, unsigned long long& y,
                                     const float* p) {
    unsigned a = (unsigned)__cvta_generic_to_shared(p);
    asm volatile("ld.shared.v2.b64 {%0, %1}, [%2];" : "=l"(x), "=l"(y) : "r"(a));
}

__device__ __forceinline__ void absfma2(unsigned long long& acc,
                                        unsigned long long a,
                                        unsigned long long b,
                                        unsigned long long w) {
    unsigned long long t;
    asm("add.rn.f32x2 %0, %1, %2;" : "=l"(t) : "l"(a), "l"(b));
    asm("and.b64 %0, %0, 0x7FFFFFFF7FFFFFFF;" : "+l"(t));
    asm("fma.rn.f32x2 %0, %1, %2, %0;" : "+l"(acc) : "l"(t), "l"(w));
}

// ---------------- K6 (fused): agg-layers (blocks 0..255, 8 nodes each) + scores (256..1279) ----------------
// __launch_bounds__(256, 2) caps regs at 128 -> guaranteed >=2 blocks/SM -> n_conc >= 296 > AGGB=256,
// so all agg blocks are wave-1 resident and the inter-phase spin barrier cannot deadlock.
struct SmemU {
    union {
        struct {
            float As[64 * 68];
            float Bs[64 * 68];
            float Ws[64];
            float sAl[64];
            float sBl[64];
        } sc;
        struct {
            float s1[8];
            float s2[8];
            float sh[4][HD];
        } ag;
    };
};

__global__ __launch_bounds__(256, 2) void k_fused(
    const float* __restrict__ bc1, const float* __restrict__ g1,
    const float* __restrict__ be1, const float* __restrict__ Wc2,
    const float* __restrict__ bc2, const float* __restrict__ g2,
    const float* __restrict__ be2, const float* __restrict__ Wout,
    const float* __restrict__ bout, float* __restrict__ node_pred,
    const float* __restrict__ Wi2,  const float* __restrict__ bi2,
    float* __restrict__ scores) {
    __shared__ __align__(16) SmemU su;
    int tid = threadIdx.x;

    if (blockIdx.x < AGGB) {
        // ------- layer 1 for 8 nodes (two quads), barrier, layer 2 + node_pred -------
        int g = tid >> 6;
        int k = tid & 63;
        int l = tid & 31;
#pragma unroll
        for (int half = 0; half < 2; half++) {
            int n = blockIdx.x * 8 + half * 4 + g;
            float sum = agg_edge64(g_hw1, n, k, l);
            float val = sum + g_dself[n] * g_hw1[n * HD + k] + bc1[k];
            float tot = gsum64(val, su.ag.s1, g, tid);
            float mu  = tot * (1.0f / 64.0f);
            float d   = val - mu;
            float vt  = gsum64(d * d, su.ag.s2, g, tid);
            float var = vt * (1.0f / 64.0f);
            su.ag.sh[g][k] = fmaxf(d * rsqrtf(var + EPSV) * g1[k] + be1[k], 0.0f);
            __syncthreads();
            float o = 0.f;
#pragma unroll 8
            for (int i = 0; i < HD; i++)
                o = fmaf(su.ag.sh[g][i], Wc2[i * HD + k], o);
            g_hw2[n * HD + k] = o;
            __syncthreads();
        }
        // barrier among agg blocks only
        __threadfence();
        if (tid == 0) {
            atomicAdd(&g_barc, 1u);
            while (*((volatile unsigned*)&g_barc) < (unsigned)AGGB)
                __nanosleep(40);
        }
        __syncthreads();
        __threadfence();
#pragma unroll
        for (int half = 0; half < 2; half++) {
            int n = blockIdx.x * 8 + half * 4 + g;
            float sum = agg_edge64(g_hw2, n, k, l);
            float val = sum + g_dself[n] * g_hw2[n * HD + k] + bc2[k];
            float tot = gsum64(val, su.ag.s1, g, tid);
            float mu  = tot * (1.0f / 64.0f);
            float d   = val - mu;
            float vt  = gsum64(d * d, su.ag.s2, g, tid);
            float var = vt * (1.0f / 64.0f);
            su.ag.sh[g][k] = fmaxf(d * rsqrtf(var + EPSV) * g2[k] + be2[k], 0.0f);
            __syncthreads();
            if (k < OUTD) {
                float o = bout[k];
#pragma unroll 8
                for (int i = 0; i < HD; i++)
                    o = fmaf(su.ag.sh[g][i], Wout[i * OUTD + k], o);
                node_pred[n * OUTD + k] = o;
            }
            __syncthreads();
        }
        return;
    }

    // ------- scores tile (relu split; pipe-balanced and-abs) -------
    int tix = blockIdx.x - AGGB;
    int i0 = (tix >> 5) * 64, j0 = (tix & 31) * 64;
    int tx = tid & 15, ty = tid >> 4;

    for (int idx = tid; idx < 4096; idx += 256) {
        int i = idx >> 6, h = idx & 63;
        su.sc.As[i * 68 + h] = g_A[(i0 + i) * HD + h];
        su.sc.Bs[i * 68 + h] = g_B[(j0 + i) * HD + h];
    }
    if (tid < 64) {
        su.sc.Ws[tid]  = Wi2[tid];
        su.sc.sAl[tid] = g_alpha[i0 + tid];
        su.sc.sBl[tid] = g_beta [j0 + tid];
    }
    __syncthreads();

    unsigned long long acc[4][4];
#pragma unroll
    for (int ii = 0; ii < 4; ii++)
#pragma unroll
        for (int jj = 0; jj < 4; jj++) acc[ii][jj] = 0ull;

    const float* ap = su.sc.As + ty * 68;
    const float* bp = su.sc.Bs + tx * 68;
#pragma unroll 2
    for (int h = 0; h < 64; h += 4) {
        unsigned long long a0[4], a1[4], b0[4], b1[4], w0, w1;
        lds2(w0, w1, su.sc.Ws + h);
#pragma unroll
        for (int ii = 0; ii < 4; ii++)
            lds2(a0[ii], a1[ii], ap + ii * (16 * 68) + h);
#pragma unroll
        for (int jj = 0; jj < 4; jj++)
            lds2(b0[jj], b1[jj], bp + jj * (16 * 68) + h);
#pragma unroll
        for (int ii = 0; ii < 4; ii++)
#pragma unroll
            for (int jj = 0; jj < 4; jj++) {
                absfma2(acc[ii][jj], a0[ii], b0[jj], w0);
                absfma2(acc[ii][jj], a1[ii], b1[jj], w1);
            }
    }

    float b2 = bi2[0];
#pragma unroll
    for (int ii = 0; ii < 4; ii++) {
        float al = su.sc.sAl[ii * 16 + ty];
#pragma unroll
        for (int jj = 0; jj < 4; jj++) {
            float lo, hi;
            asm("mov.b64 {%0, %1}, %2;" : "=f"(lo), "=f"(hi) : "l"(acc[ii][jj]));
            float lin = al + su.sc.sBl[jj * 16 + tx];
            int i = i0 + ii * 16 + ty;
            int j = j0 + jj * 16 + tx;
            scores[i * NN + j] = fmaf(0.5f, lin + lo + hi, b2);
        }
    }
}

// ---------------- launch ----------------
extern "C" void kernel_launch(void* const* d_in, const int* in_sizes, int n_in,
                              void* d_out, int out_size) {
    (void)out_size;
    bool sig = (in_sizes[1] == 2 * EE);
    const float* x  = (const float*)d_in[0];
    const int*   ei = (const int*)(sig ? d_in[1] : d_in[n_in - 1]);
    const float* ew = (const float*)(sig ? d_in[2] : d_in[1]);
    int wo = sig ? 3 : 2;
    const float* Wcz  = (const float*)d_in[wo + 0];
    const float* bcz  = (const float*)d_in[wo + 1];
    const float* Wlz  = (const float*)d_in[wo + 2];
    const float* blz  = (const float*)d_in[wo + 3];
    const float* Wch  = (const float*)d_in[wo + 8];
    const float* bch  = (const float*)d_in[wo + 9];
    const float* Wlh  = (const float*)d_in[wo + 10];
    const float* blh  = (const float*)d_in[wo + 11];
    const float* Wred = (const float*)d_in[wo + 12];
    const float* bred = (const float*)d_in[wo + 13];
    const float* Wc1  = (const float*)d_in[wo + 14];
    const float* bc1  = (const float*)d_in[wo + 15];
    const float* Wc2  = (const float*)d_in[wo + 16];
    const float* bc2  = (const float*)d_in[wo + 17];
    const float* g1   = (const float*)d_in[wo + 18];
    const float* be1  = (const float*)d_in[wo + 19];
    const float* g2   = (const float*)d_in[wo + 20];
    const float* be2  = (const float*)d_in[wo + 21];
    const float* Wout = (const float*)d_in[wo + 22];
    const float* bout = (const float*)d_in[wo + 23];
    const float* Wi1  = (const float*)d_in[wo + 24];
    const float* bi1  = (const float*)d_in[wo + 25];
    const float* Wi2  = (const float*)d_in[wo + 26];
    const float* bi2  = (const float*)d_in[wo + 27];

    float* outp      = (float*)d_out;
    float* node_pred = outp;
    float* scores    = outp + NN * OUTD;

    k_pre_deg<<<2 + EE / 256, 256>>>(Wcz, bcz, Wlz, blz, Wch, bch, Wlh, blh, ei, ew);
    k_scan<<<1, 1024>>>();
    k_scatter<<<EE / 256, 256>>>(ei, ew);
    k_aggX<<<NN / 2, 256>>>(x);
    k_red_plus<<<NN / 16, 256>>>(Wred, bred, Wc1, Wi1, bi1, Wi2);
    k_fused<<<AGGB + (NN / 64) * (NN / 64), 256>>>(
        bc1, g1, be1, Wc2, bc2, g2, be2, Wout, bout, node_pred,
        Wi2, bi2, scores);
}

// round 16
// speedup vs baseline: 1.2001x; 1.2001x over previous
#include <cuda_runtime.h>
#include <math.h>

#define NN    2048
#define EE    65536
#define SEQL  5
#define IND   32
#define HD    64
#define OUTD  16
#define EPSV  1e-5f
#define FULLM 0xffffffffu

// ---------------- scratch (device globals) ----------------
__device__ unsigned long long g_pk[NN];   // packed: cnt<<44 | fixed20(sum w); zeroed by k_scan each run
__device__ int    g_rank[EE];
__device__ int    g_rowptr[NN + 1];
__device__ float  g_dinv[NN];
__device__ float  g_dself[NN];
__device__ float2 g_csr[EE];              // (src as int bits, norm)

__device__ float  g_Wzl[IND * HD];        // Wcz @ Wlz[:HD]
__device__ float  g_Whl[IND * HD];        // Wch @ Wlh[:HD]
__device__ float  g_biasz[HD];
__device__ float  g_biash[HD];

__device__ float  g_y  [SEQL * NN * IND]; // aggregated x: [t][n][32]
__device__ float  g_hw1[NN * HD];
__device__ float  g_hw2[NN * HD];
__device__ float  g_A  [NN * HD];
__device__ float  g_B  [NN * HD];
__device__ float  g_alpha[NN];
__device__ float  g_beta [NN];

// ---------------- K1: combined gate weights (blocks 0-1, smem-staged) + degree atomics ----------------
__global__ __launch_bounds__(256) void k_pre_deg(
    const float* __restrict__ Wcz, const float* __restrict__ bcz,
    const float* __restrict__ Wlz, const float* __restrict__ blz,
    const float* __restrict__ Wch, const float* __restrict__ bch,
    const float* __restrict__ Wlh, const float* __restrict__ blh,
    const int* __restrict__ ei,    const float* __restrict__ ew) {
    int b = blockIdx.x;
    int tid = threadIdx.x;
    if (b >= 2) {                     // degree + per-edge rank via one packed atomic
        int e = (b - 2) * 256 + tid;
        int dst = ei[EE + e];
        unsigned fixw = __float2uint_rn(ew[e] * 1048576.0f);   // w in [0,1)
        unsigned long long pk = (1ull << 44) | (unsigned long long)fixw;
        unsigned long long old = atomicAdd(&g_pk[dst], pk);
        g_rank[e] = (int)(old >> 44);
        return;
    }
    __shared__ __align__(16) float sWl[HD * HD];
    __shared__ __align__(16) float sWc[IND * HD];
    bool z = (b == 0);
    const float* Wc = z ? Wcz : Wch;
    const float* Wl = z ? Wlz : Wlh;
    const float* bc = z ? bcz : bch;
    const float* bl = z ? blz : blh;
    float* Wo = z ? g_Wzl : g_Whl;
    float* bo = z ? g_biasz : g_biash;
#pragma unroll
    for (int q = 0; q < 4; q++)
        ((float4*)sWl)[tid + 256 * q] = ((const float4*)Wl)[tid + 256 * q];
#pragma unroll
    for (int q = 0; q < 2; q++)
        ((float4*)sWc)[tid + 256 * q] = ((const float4*)Wc)[tid + 256 * q];
    __syncthreads();
#pragma unroll
    for (int q = 0; q < 8; q++) {
        int o = tid + 256 * q;        // o < 2048
        int i = o >> 6, k = o & 63;
        float acc = 0.f;
#pragma unroll 8
        for (int m = 0; m < HD; m++)
            acc = fmaf(sWc[i * HD + m], sWl[m * HD + k], acc);
        Wo[o] = acc;
    }
    if (tid < HD) {
        float acc = bl[tid];
#pragma unroll 8
        for (int m = 0; m < HD; m++)
            acc = fmaf(bc[m], sWl[m * HD + tid], acc);
        bo[tid] = acc;
    }
}

// ---------------- K2: scan counts -> rowptr; deg -> dinv/dself; re-zero g_pk ----------------
__global__ void k_scan() {
    __shared__ int s[1024];
    int t = threadIdx.x;
    unsigned long long p0 = g_pk[2 * t];
    unsigned long long p1 = g_pk[2 * t + 1];
    g_pk[2 * t] = 0ull;               // reset for the next run (graph replay)
    g_pk[2 * t + 1] = 0ull;
    int a = (int)(p0 >> 44);
    int b = (int)(p1 >> 44);
    int pairsum = a + b;
    s[t] = pairsum;
    for (int off = 1; off < 1024; off <<= 1) {
        __syncthreads();
        int v = (t >= off) ? s[t - off] : 0;
        __syncthreads();
        s[t] += v;
    }
    __syncthreads();
    int incl = s[t];
    int excl = incl - pairsum;
    g_rowptr[2 * t]     = excl;
    g_rowptr[2 * t + 1] = excl + a;
    if (t == 1023) g_rowptr[NN] = incl;

    const float inv20 = 1.0f / 1048576.0f;
    const unsigned long long mask = (1ull << 44) - 1;
    float d0 = (float)(double)(p0 & mask) * inv20 + 1.0f;
    float d1 = (float)(double)(p1 & mask) * inv20 + 1.0f;
    float i0 = rsqrtf(d0), i1 = rsqrtf(d1);
    g_dinv[2 * t] = i0;      g_dself[2 * t] = i0 * i0;
    g_dinv[2 * t + 1] = i1;  g_dself[2 * t + 1] = i1 * i1;
}

// ---------------- K3: scatter (atomic-free; position known) ----------------
__global__ __launch_bounds__(256) void k_scatter(const int* __restrict__ ei,
                                                 const float* __restrict__ ew) {
    int e = blockIdx.x * 256 + threadIdx.x;
    int src = ei[e];
    int dst = ei[EE + e];
    int pos = g_rowptr[dst] + g_rank[e];
    g_csr[pos] = make_float2(__int_as_float(src),
                             g_dinv[src] * ew[e] * g_dinv[dst]);
}

// ---------------- K4: aggregate RAW x; warp = (node, edge-quarter), all 5 t ----------------
__global__ __launch_bounds__(256) void k_aggX(const float* __restrict__ x) {
    __shared__ float part[8][SEQL][32];      // 5KB
    int tid = threadIdx.x;
    int wid = tid >> 5;
    int l = tid & 31;                        // feature index
    int node = wid >> 2;                     // 0..1
    int q = wid & 3;
    int n = blockIdx.x * 2 + node;
    int beg = g_rowptr[n], end = g_rowptr[n + 1];
    int len = end - beg;
    int qbeg = beg + ((len * q) >> 2);
    int qend = beg + ((len * (q + 1)) >> 2);

    float a0 = 0.f, a1 = 0.f, a2 = 0.f, a3 = 0.f, a4 = 0.f;
    for (int base = qbeg; base < qend; base += 32) {
        int m = qend - base; if (m > 32) m = 32;
        float2 ce = (base + l < qend) ? g_csr[base + l] : make_float2(0.f, 0.f);
        int cs = __float_as_int(ce.x);
#pragma unroll 8
        for (int i = 0; i < m; i++) {
            int   s  = __shfl_sync(FULLM, cs, i);
            float wt = __shfl_sync(FULLM, ce.y, i);
            const float* xs = x + s * IND + l;
            a0 = fmaf(wt, xs[0 * NN * IND], a0);
            a1 = fmaf(wt, xs[1 * NN * IND], a1);
            a2 = fmaf(wt, xs[2 * NN * IND], a2);
            a3 = fmaf(wt, xs[3 * NN * IND], a3);
            a4 = fmaf(wt, xs[4 * NN * IND], a4);
        }
    }
    part[wid][0][l] = a0;
    part[wid][1][l] = a1;
    part[wid][2][l] = a2;
    part[wid][3][l] = a3;
    part[wid][4][l] = a4;
    __syncthreads();

    if (tid < 160) {
        int nd = tid >= 80 ? 1 : 0;
        int rem = tid - nd * 80;         // (t, l-pair): t = rem/16, l = (rem%16)*2
        int t  = rem / 16;
        int l2 = (rem % 16) * 2;
        int w0 = nd * 4;
        int n2 = blockIdx.x * 2 + nd;
        float ds = g_dself[n2];
#pragma unroll
        for (int u = 0; u < 2; u++) {
            int ll = l2 + u;
            float sv = part[w0][t][ll] + part[w0 + 1][t][ll]
                     + part[w0 + 2][t][ll] + part[w0 + 3][t][ll];
            sv = fmaf(ds, x[(t * NN + n2) * IND + ll], sv);
            g_y[(t * NN + n2) * IND + ll] = sv;
        }
    }
}

// ---------------- K5: gates + emb=H@Wred+bred; hw1/A/B; alpha/beta (16 nodes/block) ----------------
__global__ __launch_bounds__(256) void k_red_plus(
    const float* __restrict__ Wred, const float* __restrict__ bred,
    const float* __restrict__ Wc1,
    const float* __restrict__ Wi1,  const float* __restrict__ bi1,
    const float* __restrict__ Wi2) {
    __shared__ __align__(16) float sH[16 * SEQL * HD];  // 20KB
    __shared__ __align__(16) float wt[HD * HD];         // 16KB
    __shared__ __align__(16) union {
        float sy[16 * SEQL * IND];
        float sE[16 * HD];
    } u;
    __shared__ float sWi2[HD];
    __shared__ float red[8][4];
    int tid = threadIdx.x;
    int k = tid & 63;
    int rgrp = tid >> 6;
    int warpid = tid >> 5;
    int rowbase = blockIdx.x * 16;

#pragma unroll
    for (int t = 0; t < SEQL; t++) {
        if (tid < 128)
            ((float4*)(u.sy + t * 512))[tid] =
                ((const float4*)(g_y + (t * NN + rowbase) * IND))[tid];
    }
#pragma unroll
    for (int q = 0; q < 8; q++) {
        int idx = tid + 256 * q;
        ((float2*)wt)[idx] = make_float2(g_Wzl[idx], g_Whl[idx]);
    }
    if (tid < HD) sWi2[tid] = Wi2[tid];
    __syncthreads();

    {
        float bz = g_biasz[k], bh = g_biash[k];
#pragma unroll 4
        for (int rr = 0; rr < 20; rr++) {
            int rid = rgrp * 20 + rr;
            int t = rid >> 4, node = rid & 15;
            const float* yr = u.sy + (t * 16 + node) * IND;
            float az = bz, ah = bh;
#pragma unroll
            for (int i = 0; i < IND; i++) {
                float2 w2 = ((const float2*)wt)[i * HD + k];
                float yv = yr[i];
                az = fmaf(yv, w2.x, az);
                ah = fmaf(yv, w2.y, ah);
            }
            float Z  = 1.0f / (1.0f + expf(-az));
            float Ht = tanhf(ah);
            sH[node * (SEQL * HD) + t * HD + k] = (1.0f - Z) * Ht;
        }
    }
    __syncthreads();

    float acc[4];
    float br = bred[k];
#pragma unroll
    for (int rr = 0; rr < 4; rr++) acc[rr] = br;
    for (int c = 0; c < SEQL; c++) {
#pragma unroll
        for (int q = 0; q < 4; q++)
            ((float4*)wt)[tid + 256 * q] = ((const float4*)(Wred + c * HD * HD))[tid + 256 * q];
        __syncthreads();
#pragma unroll 8
        for (int i = 0; i < HD; i++) {
            float w = wt[i * HD + k];
#pragma unroll
            for (int rr = 0; rr < 4; rr++)
                acc[rr] = fmaf(sH[(rgrp * 4 + rr) * (SEQL * HD) + c * HD + i], w, acc[rr]);
        }
        __syncthreads();
    }
#pragma unroll
    for (int rr = 0; rr < 4; rr++)
        u.sE[(rgrp * 4 + rr) * HD + k] = acc[rr];

#pragma unroll
    for (int q = 0; q < 4; q++)
        ((float4*)wt)[tid + 256 * q] = ((const float4*)Wc1)[tid + 256 * q];
    __syncthreads();
#pragma unroll
    for (int rr = 0; rr < 4; rr++) acc[rr] = 0.f;
#pragma unroll 8
    for (int i = 0; i < HD; i++) {
        float w = wt[i * HD + k];
#pragma unroll
        for (int rr = 0; rr < 4; rr++)
            acc[rr] = fmaf(u.sE[(rgrp * 4 + rr) * HD + i], w, acc[rr]);
    }
#pragma unroll
    for (int rr = 0; rr < 4; rr++)
        g_hw1[(rowbase + rgrp * 4 + rr) * HD + k] = acc[rr];

    __syncthreads();
#pragma unroll
    for (int q = 0; q < 4; q++)
        ((float4*)wt)[tid + 256 * q] = ((const float4*)Wi1)[tid + 256 * q];
    __syncthreads();
    float b1 = bi1[k];
#pragma unroll
    for (int rr = 0; rr < 4; rr++) acc[rr] = b1;
#pragma unroll 8
    for (int i = 0; i < HD; i++) {
        float w = wt[i * HD + k];
#pragma unroll
        for (int rr = 0; rr < 4; rr++)
            acc[rr] = fmaf(u.sE[(rgrp * 4 + rr) * HD + i], w, acc[rr]);
    }
    {
        float w2 = sWi2[k];
        float pa[4];
#pragma unroll
        for (int rr = 0; rr < 4; rr++) {
            g_A[(rowbase + rgrp * 4 + rr) * HD + k] = acc[rr];
            pa[rr] = acc[rr] * w2;
#pragma unroll
            for (int off = 16; off > 0; off >>= 1)
                pa[rr] += __shfl_xor_sync(FULLM, pa[rr], off);
        }
        if ((tid & 31) == 0)
#pragma unroll
            for (int rr = 0; rr < 4; rr++) red[warpid][rr] = pa[rr];
        __syncthreads();
        if (k < 4)
            g_alpha[rowbase + rgrp * 4 + k] = red[rgrp * 2][k] + red[rgrp * 2 + 1][k];
    }

    __syncthreads();
#pragma unroll
    for (int q = 0; q < 4; q++)
        ((float4*)wt)[tid + 256 * q] = ((const float4*)(Wi1 + HD * HD))[tid + 256 * q];
    __syncthreads();
#pragma unroll
    for (int rr = 0; rr < 4; rr++) acc[rr] = 0.f;
#pragma unroll 8
    for (int i = 0; i < HD; i++) {
        float w = wt[i * HD + k];
#pragma unroll
        for (int rr = 0; rr < 4; rr++)
            acc[rr] = fmaf(u.sE[(rgrp * 4 + rr) * HD + i], w, acc[rr]);
    }
    {
        float w2 = sWi2[k];
        float pb[4];
#pragma unroll
        for (int rr = 0; rr < 4; rr++) {
            g_B[(rowbase + rgrp * 4 + rr) * HD + k] = acc[rr];
            pb[rr] = acc[rr] * w2;
#pragma unroll
            for (int off = 16; off > 0; off >>= 1)
                pb[rr] += __shfl_xor_sync(FULLM, pb[rr], off);
        }
        __syncthreads();
        if ((tid & 31) == 0)
#pragma unroll
            for (int rr = 0; rr < 4; rr++) red[warpid][rr] = pb[rr];
        __syncthreads();
        if (k < 4)
            g_beta[rowbase + rgrp * 4 + k] = red[rgrp * 2][k] + red[rgrp * 2 + 1][k];
    }
}

// ---------------- warp-staged GCN aggregation over a 64-wide feature row ----------------
__device__ __forceinline__ float agg_edge64(const float* __restrict__ feat,
                                            int n, int k, int l) {
    int beg = g_rowptr[n], end = g_rowptr[n + 1];
    float sum = 0.f;
    for (int base = beg; base < end; base += 32) {
        int m = end - base; if (m > 32) m = 32;
        float2 ce = (base + l < end) ? g_csr[base + l] : make_float2(0.f, 0.f);
        int   cs = __float_as_int(ce.x);
        for (int i = 0; i < m; i++) {
            int   s  = __shfl_sync(FULLM, cs, i);
            float wt = __shfl_sync(FULLM, ce.y, i);
            sum = fmaf(wt, feat[s * HD + k], sum);
        }
    }
    return sum;
}

// group-of-64 sum helper
__device__ __forceinline__ float gsum64(float v, float* slots, int g, int tid) {
#pragma unroll
    for (int off = 16; off > 0; off >>= 1)
        v += __shfl_xor_sync(FULLM, v, off);
    if ((tid & 31) == 0) slots[tid >> 5] = v;
    __syncthreads();
    return slots[g * 2] + slots[g * 2 + 1];
}

// ---------------- K6: agg(hw1)+LN+relu -> smem; hw2 = h1@Wc2; 4 nodes/block ----------------
__global__ __launch_bounds__(256) void k_agg1(
    const float* __restrict__ bc1, const float* __restrict__ g1,
    const float* __restrict__ be1, const float* __restrict__ Wc2) {
    __shared__ float s1[8], s2[8];
    __shared__ float sh[4][HD];
    int tid = threadIdx.x;
    int g = tid >> 6;
    int n = blockIdx.x * 4 + g;
    int k = tid & 63;
    int l = tid & 31;
    float sum = agg_edge64(g_hw1, n, k, l);
    float val = sum + g_dself[n] * g_hw1[n * HD + k] + bc1[k];
    float tot = gsum64(val, s1, g, tid);
    float mu  = tot * (1.0f / 64.0f);
    float d   = val - mu;
    float vt  = gsum64(d * d, s2, g, tid);
    float var = vt * (1.0f / 64.0f);
    sh[g][k] = fmaxf(d * rsqrtf(var + EPSV) * g1[k] + be1[k], 0.0f);
    __syncthreads();
    float o = 0.f;
#pragma unroll 8
    for (int i = 0; i < HD; i++)
        o = fmaf(sh[g][i], Wc2[i * HD + k], o);
    g_hw2[n * HD + k] = o;
}

// ---------------- K7: agg(hw2)+LN+relu; node_pred = h2@Wout+bout ----------------
__global__ __launch_bounds__(256) void k_agg2(
    const float* __restrict__ bc2, const float* __restrict__ g2,
    const float* __restrict__ be2, const float* __restrict__ Wout,
    const float* __restrict__ bout, float* __restrict__ node_pred) {
    __shared__ float s1[8], s2[8];
    __shared__ float sh[4][HD];
    int tid = threadIdx.x;
    int g = tid >> 6;
    int n = blockIdx.x * 4 + g;
    int k = tid & 63;
    int l = tid & 31;
    float sum = agg_edge64(g_hw2, n, k, l);
    float val = sum + g_dself[n] * g_hw2[n * HD + k] + bc2[k];
    float tot = gsum64(val, s1, g, tid);
    float mu  = tot * (1.0f / 64.0f);
    float d   = val - mu;
    float vt  = gsum64(d * d, s2, g, tid);
    float var = vt * (1.0f / 64.0f);
    sh[g][k] = fmaxf(d * rsqrtf(var + EPSV) * g2[k] + be2[k], 0.0f);
    __syncthreads();
    if (k < OUTD) {
        float o = bout[k];
#pragma unroll 8
        for (int i = 0; i < HD; i++)
            o = fmaf(sh[g][i], Wout[i * OUTD + k], o);
        node_pred[n * OUTD + k] = o;
    }
}

// ---------------- K8: scores via relu split; pipe-balanced and.b64 abs ----------------
__device__ __forceinline__ void lds2(unsigned long long& x, unsigned long long& y,
                                     const float* p) {
    unsigned a = (unsigned)__cvta_generic_to_shared(p);
    asm volatile("ld.shared.v2.b64 {%0, %1}, [%2];" : "=l"(x), "=l"(y) : "r"(a));
}

__device__ __forceinline__ void absfma2(unsigned long long& acc,
                                        unsigned long long a,
                                        unsigned long long b,
                                        unsigned long long w) {
    unsigned long long t;
    asm("add.rn.f32x2 %0, %1, %2;" : "=l"(t) : "l"(a), "l"(b));
    asm("and.b64 %0, %0, 0x7FFFFFFF7FFFFFFF;" : "+l"(t));
    asm("fma.rn.f32x2 %0, %1, %2, %0;" : "+l"(acc) : "l"(t), "l"(w));
}

__global__ __launch_bounds__(256) void k_scores(const float* __restrict__ Wi2,
                                                const float* __restrict__ bi2,
                                                float* __restrict__ scores) {
    __shared__ __align__(16) float As[64 * 68];
    __shared__ __align__(16) float Bs[64 * 68];
    __shared__ __align__(16) float Ws[64];
    __shared__ float sAl[64], sBl[64];
    int tid = threadIdx.x;
    int tx = tid & 15, ty = tid >> 4;
    int i0 = blockIdx.y * 64, j0 = blockIdx.x * 64;

    for (int idx = tid; idx < 4096; idx += 256) {
        int i = idx >> 6, h = idx & 63;
        As[i * 68 + h] = g_A[(i0 + i) * HD + h];
        Bs[i * 68 + h] = g_B[(j0 + i) * HD + h];
    }
    if (tid < 64) {
        Ws[tid]  = Wi2[tid];
        sAl[tid] = g_alpha[i0 + tid];
        sBl[tid] = g_beta [j0 + tid];
    }
    __syncthreads();

    unsigned long long acc[4][4];
#pragma unroll
    for (int ii = 0; ii < 4; ii++)
#pragma unroll
        for (int jj = 0; jj < 4; jj++) acc[ii][jj] = 0ull;

    const float* ap = As + ty * 68;
    const float* bp = Bs + tx * 68;
#pragma unroll 2
    for (int h = 0; h < 64; h += 4) {
        unsigned long long a0[4], a1[4], b0[4], b1[4], w0, w1;
        lds2(w0, w1, Ws + h);
#pragma unroll
        for (int ii = 0; ii < 4; ii++)
            lds2(a0[ii], a1[ii], ap + ii * (16 * 68) + h);
#pragma unroll
        for (int jj = 0; jj < 4; jj++)
            lds2(b0[jj], b1[jj], bp + jj * (16 * 68) + h);
#pragma unroll
        for (int ii = 0; ii < 4; ii++)
#pragma unroll
            for (int jj = 0; jj < 4; jj++) {
                absfma2(acc[ii][jj], a0[ii], b0[jj], w0);
                absfma2(acc[ii][jj], a1[ii], b1[jj], w1);
            }
    }

    float b2 = bi2[0];
#pragma unroll
    for (int ii = 0; ii < 4; ii++) {
        float al = sAl[ii * 16 + ty];
#pragma unroll
        for (int jj = 0; jj < 4; jj++) {
            float lo, hi;
            asm("mov.b64 {%0, %1}, %2;" : "=f"(lo), "=f"(hi) : "l"(acc[ii][jj]));
            float lin = al + sBl[jj * 16 + tx];
            int i = i0 + ii * 16 + ty;
            int j = j0 + jj * 16 + tx;
            scores[i * NN + j] = fmaf(0.5f, lin + lo + hi, b2);
        }
    }
}

// ---------------- launch: forked-stream graph (agg chain || scores) ----------------
extern "C" void kernel_launch(void* const* d_in, const int* in_sizes, int n_in,
                              void* d_out, int out_size) {
    (void)out_size;
    // Lazy one-time stream/event init. First call is the uncaptured correctness
    // run, so creation happens OUTSIDE graph capture; later captured calls only
    // record/wait (both capturable ops). No device memory is allocated.
    static cudaStream_t s_side = nullptr;
    static cudaEvent_t  s_fork = nullptr, s_join = nullptr;
    if (s_side == nullptr) {
        cudaStreamCreateWithFlags(&s_side, cudaStreamNonBlocking);
        cudaEventCreateWithFlags(&s_fork, cudaEventDisableTiming);
        cudaEventCreateWithFlags(&s_join, cudaEventDisableTiming);
    }

    bool sig = (in_sizes[1] == 2 * EE);
    const float* x  = (const float*)d_in[0];
    const int*   ei = (const int*)(sig ? d_in[1] : d_in[n_in - 1]);
    const float* ew = (const float*)(sig ? d_in[2] : d_in[1]);
    int wo = sig ? 3 : 2;
    const float* Wcz  = (const float*)d_in[wo + 0];
    const float* bcz  = (const float*)d_in[wo + 1];
    const float* Wlz  = (const float*)d_in[wo + 2];
    const float* blz  = (const float*)d_in[wo + 3];
    const float* Wch  = (const float*)d_in[wo + 8];
    const float* bch  = (const float*)d_in[wo + 9];
    const float* Wlh  = (const float*)d_in[wo + 10];
    const float* blh  = (const float*)d_in[wo + 11];
    const float* Wred = (const float*)d_in[wo + 12];
    const float* bred = (const float*)d_in[wo + 13];
    const float* Wc1  = (const float*)d_in[wo + 14];
    const float* bc1  = (const float*)d_in[wo + 15];
    const float* Wc2  = (const float*)d_in[wo + 16];
    const float* bc2  = (const float*)d_in[wo + 17];
    const float* g1   = (const float*)d_in[wo + 18];
    const float* be1  = (const float*)d_in[wo + 19];
    const float* g2   = (const float*)d_in[wo + 20];
    const float* be2  = (const float*)d_in[wo + 21];
    const float* Wout = (const float*)d_in[wo + 22];
    const float* bout = (const float*)d_in[wo + 23];
    const float* Wi1  = (const float*)d_in[wo + 24];
    const float* bi1  = (const float*)d_in[wo + 25];
    const float* Wi2  = (const float*)d_in[wo + 26];
    const float* bi2  = (const float*)d_in[wo + 27];

    float* outp      = (float*)d_out;
    float* node_pred = outp;
    float* scores    = outp + NN * OUTD;

    // serial prefix on the default (captured-origin) stream
    k_pre_deg<<<2 + EE / 256, 256>>>(Wcz, bcz, Wlz, blz, Wch, bch, Wlh, blh, ei, ew);
    k_scan<<<1, 1024>>>();
    k_scatter<<<EE / 256, 256>>>(ei, ew);
    k_aggX<<<NN / 2, 256>>>(x);
    k_red_plus<<<NN / 16, 256>>>(Wred, bred, Wc1, Wi1, bi1, Wi2);

    // fork: agg chain on side stream, scores on main stream, then join
    cudaEventRecord(s_fork, 0);
    cudaStreamWaitEvent(s_side, s_fork, 0);
    k_agg1<<<NN / 4, 256, 0, s_side>>>(bc1, g1, be1, Wc2);
    k_agg2<<<NN / 4, 256, 0, s_side>>>(bc2, g2, be2, Wout, bout, node_pred);
    cudaEventRecord(s_join, s_side);

    dim3 sgrid(NN / 64, NN / 64);
    k_scores<<<sgrid, 256>>>(Wi2, bi2, scores);
    cudaStreamWaitEvent(0, s_join, 0);
}